// round 2
// baseline (speedup 1.0000x reference)
#include <cuda_runtime.h>
#include <math.h>

// Problem dims (fixed by the reference)
#define B_   4
#define T_   1024
#define MM_  1024      // mem length
#define D_   1024
#define H_   16
#define DH_  64
#define L_   2048      // T + M
#define DFF_ 4096

// ---------------- scratch (device globals: no allocation allowed) ----------
__device__ float g_xn [B_*T_*D_];            // LN1(x)
__device__ float g_cat[B_*L_*D_];            // [mem ; xn]
__device__ float g_q  [B_*T_*D_];            // xn @ Wq    [B*T, D]
__device__ float g_k  [B_*L_*D_];            // cat @ Wk   [B*L, D]
__device__ float g_v  [B_*L_*D_];            // cat @ Wv   [B*L, D]
__device__ float g_pe [L_*D_];               // pos emb
__device__ float g_r  [L_*D_];               // pe @ Wr    [L, D]
__device__ float g_sc [B_*H_*T_*L_];         // content scores -> probs (in place)
__device__ float g_rel[B_*H_*T_*L_];         // rel scores (pre-shift)
__device__ float g_ao [B_*T_*D_];            // attention out [b,i,h,d] == [B*T, D]
__device__ float g_x2 [B_*T_*D_];            // residual + attn proj
__device__ float g_xf [B_*T_*D_];            // LN2(x2)
__device__ float g_ffh[B_*T_*DFF_];          // gelu(xf@W1+b1)

// ---------------- positional embedding ------------------------------------
__global__ void posemb_kernel() {
    int idx = blockIdx.x * 256 + threadIdx.x;
    if (idx >= L_ * D_) return;
    int l = idx / D_, d = idx % D_;
    int i = (d < D_ / 2) ? d : d - D_ / 2;
    float inv = (float)(1.0 / pow(10000.0, (2.0 * i) / (double)D_));
    float pos = (float)(L_ - 1 - l);
    float arg = pos * inv;                 // float32 product, matches np.outer(f32)
    double s = (d < D_ / 2) ? sin((double)arg) : cos((double)arg);
    g_pe[idx] = (float)s;
}

// ---------------- layer norm (row of D=1024, block=256) --------------------
__global__ void ln_kernel(const float* __restrict__ in, float* __restrict__ out,
                          const float* __restrict__ g, const float* __restrict__ b) {
    __shared__ float red[256];
    int row = blockIdx.x, tid = threadIdx.x;
    const float* p = in + (size_t)row * D_;
    float v[4];
    float s = 0.f;
#pragma unroll
    for (int j = 0; j < 4; j++) { v[j] = p[tid + j * 256]; s += v[j]; }
    red[tid] = s; __syncthreads();
    for (int o = 128; o > 0; o >>= 1) { if (tid < o) red[tid] += red[tid + o]; __syncthreads(); }
    float mu = red[0] * (1.0f / D_);
    __syncthreads();
    float vs = 0.f;
#pragma unroll
    for (int j = 0; j < 4; j++) { float dd = v[j] - mu; vs += dd * dd; }
    red[tid] = vs; __syncthreads();
    for (int o = 128; o > 0; o >>= 1) { if (tid < o) red[tid] += red[tid + o]; __syncthreads(); }
    float inv = rsqrtf(red[0] * (1.0f / D_) + 1e-5f);
    float* q = out + (size_t)row * D_;
#pragma unroll
    for (int j = 0; j < 4; j++) {
        int c = tid + j * 256;
        q[c] = (v[j] - mu) * inv * g[c] + b[c];
    }
}

// ---------------- concat [mem ; xn] ----------------------------------------
__global__ void concat_kernel(const float* __restrict__ mem) {
    size_t idx = (size_t)blockIdx.x * 256 + threadIdx.x;   // total B*L*D
    int b = (int)(idx / ((size_t)L_ * D_));
    int rem = (int)(idx % ((size_t)L_ * D_));
    int l = rem / D_, d = rem % D_;
    g_cat[idx] = (l < MM_) ? mem[((size_t)b * MM_ + l) * D_ + d]
                           : g_xn[((size_t)b * T_ + (l - MM_)) * D_ + d];
}

// ---------------- generic 128x128x16 fp32 GEMM -----------------------------
// EPI: 0=none, 1=+bias, 2=gelu(.+bias), 3=+res, 4=+bias+res
__device__ __forceinline__ float gelu_exact(float x) {
    return 0.5f * x * (1.0f + erff(x * 0.70710678118654752f));
}

template <int EPI>
__global__ __launch_bounds__(256)
void gemm_kernel(const float* __restrict__ A, const float* __restrict__ Bp,
                 float* __restrict__ C, int M, int N, int K,
                 const float* __restrict__ bias, const float* __restrict__ res) {
    __shared__ float As[16][130];
    __shared__ float Bs[16][128];
    int bm = blockIdx.y * 128, bn = blockIdx.x * 128;
    int tid = threadIdx.x;
    int tx = tid & 15, ty = tid >> 4;
    int arow = tid >> 2;          // 0..63
    int ac   = (tid & 3) << 2;    // 0,4,8,12
    int brow = tid >> 5;          // 0..7
    int bc   = (tid & 31) << 2;   // 0..124
    float c[8][8];
#pragma unroll
    for (int i = 0; i < 8; i++)
#pragma unroll
        for (int j = 0; j < 8; j++) c[i][j] = 0.f;

    for (int k0 = 0; k0 < K; k0 += 16) {
        float4 a0 = *(const float4*)&A[(size_t)(bm + arow) * K + k0 + ac];
        float4 a1 = *(const float4*)&A[(size_t)(bm + 64 + arow) * K + k0 + ac];
        As[ac + 0][arow] = a0.x; As[ac + 1][arow] = a0.y;
        As[ac + 2][arow] = a0.z; As[ac + 3][arow] = a0.w;
        As[ac + 0][64 + arow] = a1.x; As[ac + 1][64 + arow] = a1.y;
        As[ac + 2][64 + arow] = a1.z; As[ac + 3][64 + arow] = a1.w;
        float4 b0 = *(const float4*)&Bp[(size_t)(k0 + brow) * N + bn + bc];
        float4 b1 = *(const float4*)&Bp[(size_t)(k0 + 8 + brow) * N + bn + bc];
        *(float4*)&Bs[brow][bc]     = b0;
        *(float4*)&Bs[brow + 8][bc] = b1;
        __syncthreads();
#pragma unroll
        for (int k = 0; k < 16; k++) {
            float ra[8], rb[8];
#pragma unroll
            for (int i = 0; i < 4; i++) {
                ra[i]     = As[k][ty * 4 + i];
                ra[i + 4] = As[k][64 + ty * 4 + i];
                rb[i]     = Bs[k][tx * 4 + i];
                rb[i + 4] = Bs[k][64 + tx * 4 + i];
            }
#pragma unroll
            for (int i = 0; i < 8; i++)
#pragma unroll
                for (int j = 0; j < 8; j++) c[i][j] += ra[i] * rb[j];
        }
        __syncthreads();
    }
#pragma unroll
    for (int i = 0; i < 8; i++) {
        int row = bm + ((i < 4) ? ty * 4 + i : 64 + ty * 4 + (i - 4));
#pragma unroll
        for (int j = 0; j < 8; j++) {
            int col = bn + ((j < 4) ? tx * 4 + j : 64 + tx * 4 + (j - 4));
            float v = c[i][j];
            if (EPI == 1) v += bias[col];
            if (EPI == 2) v = gelu_exact(v + bias[col]);
            if (EPI == 3) v += res[(size_t)row * N + col];
            if (EPI == 4) v += bias[col] + res[(size_t)row * N + col];
            C[(size_t)row * N + col] = v;
        }
    }
}

// ---------------- attention score kernel (content & rel) -------------------
// C[bh, i, j] = sum_d (Q[b,i,h,d] + bias[h,d]) * Bm[b?, j, h, d]
// Bm row stride is D_ (=H*dh), per-batch stride bstride (0 for r).
__global__ __launch_bounds__(256)
void score_kernel(const float* __restrict__ Q, const float* __restrict__ bias,
                  const float* __restrict__ Bm, size_t bstride,
                  float* __restrict__ C) {
    int bh = blockIdx.z, b = bh >> 4, h = bh & 15;
    int i0 = blockIdx.x << 6, j0 = blockIdx.y << 6;
    __shared__ float Qs[64][65];
    __shared__ float Ks[64][65];
    int tid = threadIdx.x;
    const float* qbase = Q + (size_t)b * T_ * D_ + h * DH_;
    const float* kbase = Bm + (size_t)b * bstride + h * DH_;
    for (int t = tid; t < 64 * 64; t += 256) {
        int r = t >> 6, d = t & 63;
        Qs[r][d] = qbase[(size_t)(i0 + r) * D_ + d] + bias[h * DH_ + d];
        Ks[r][d] = kbase[(size_t)(j0 + r) * D_ + d];
    }
    __syncthreads();
    int tx = tid & 15, ty = tid >> 4;
    float c[4][4];
#pragma unroll
    for (int i = 0; i < 4; i++)
#pragma unroll
        for (int j = 0; j < 4; j++) c[i][j] = 0.f;
#pragma unroll 8
    for (int kd = 0; kd < 64; kd++) {
        float a[4], bb[4];
#pragma unroll
        for (int i = 0; i < 4; i++) {
            a[i]  = Qs[ty * 4 + i][kd];
            bb[i] = Ks[tx * 4 + i][kd];
        }
#pragma unroll
        for (int i = 0; i < 4; i++)
#pragma unroll
            for (int j = 0; j < 4; j++) c[i][j] += a[i] * bb[j];
    }
    float* cb = C + (size_t)bh * T_ * L_;
#pragma unroll
    for (int i = 0; i < 4; i++)
#pragma unroll
        for (int j = 0; j < 4; j++)
            cb[(size_t)(i0 + ty * 4 + i) * L_ + (j0 + tx * 4 + j)] = c[i][j];
}

// ---------------- fused rel-shift + add + scale + softmax ------------------
// Row (bh, i). shift: f = i*L + j + T;  i2 = f/(L+1);  l = f%(L+1)
// value = (l>0) ? rel[bh, i2, l-1] : 0
__global__ __launch_bounds__(256)
void softmax_kernel() {
    int row = blockIdx.x;
    int bh = row >> 10;        // / T_
    int i  = row & 1023;
    size_t base = (size_t)bh * T_ * L_;
    float* P = g_sc + base + (size_t)i * L_;
    const float* R = g_rel + base;
    __shared__ float red[8];
    int tid = threadIdx.x;
    int lane = tid & 31, wid = tid >> 5;
    float v[8];
    float mx = -1e30f;
#pragma unroll
    for (int jj = 0; jj < 8; jj++) {
        int j = tid + (jj << 8);
        int f = i * L_ + j + T_;
        int i2 = f / (L_ + 1);
        int l = f - i2 * (L_ + 1);
        float rv = (l > 0) ? R[(size_t)i2 * L_ + (l - 1)] : 0.0f;
        float s = (P[j] + rv) * 0.125f;       // scale = 1/sqrt(64)
        v[jj] = s;
        mx = fmaxf(mx, s);
    }
#pragma unroll
    for (int o = 16; o > 0; o >>= 1) mx = fmaxf(mx, __shfl_xor_sync(0xffffffffu, mx, o));
    if (lane == 0) red[wid] = mx;
    __syncthreads();
    mx = red[0];
#pragma unroll
    for (int w = 1; w < 8; w++) mx = fmaxf(mx, red[w]);
    float sum = 0.f;
#pragma unroll
    for (int jj = 0; jj < 8; jj++) { v[jj] = expf(v[jj] - mx); sum += v[jj]; }
#pragma unroll
    for (int o = 16; o > 0; o >>= 1) sum += __shfl_xor_sync(0xffffffffu, sum, o);
    __syncthreads();
    if (lane == 0) red[wid] = sum;
    __syncthreads();
    sum = 0.f;
#pragma unroll
    for (int w = 0; w < 8; w++) sum += red[w];
    float inv = 1.0f / sum;
#pragma unroll
    for (int jj = 0; jj < 8; jj++) P[tid + (jj << 8)] = v[jj] * inv;
}

// ---------------- probs @ V ------------------------------------------------
// out[b,i,h,d] = sum_j probs[bh,i,j] * v[b,j,h,d]
__global__ __launch_bounds__(256)
void pv_kernel() {
    int bh = blockIdx.y, b = bh >> 4, h = bh & 15;
    int i0 = blockIdx.x << 6;
    __shared__ float Ps[64][65];
    __shared__ float Vs[64][65];
    int tid = threadIdx.x;
    int tx = tid & 15, ty = tid >> 4;
    float c[4][4];
#pragma unroll
    for (int i = 0; i < 4; i++)
#pragma unroll
        for (int j = 0; j < 4; j++) c[i][j] = 0.f;
    const float* P = g_sc + (size_t)bh * T_ * L_;
    const float* V = g_v + (size_t)b * L_ * D_ + h * DH_;
    for (int jc = 0; jc < L_; jc += 64) {
        for (int t = tid; t < 64 * 64; t += 256) {
            int r = t >> 6, d2 = t & 63;
            Ps[r][d2] = P[(size_t)(i0 + r) * L_ + jc + d2];
            Vs[r][d2] = V[(size_t)(jc + r) * D_ + d2];
        }
        __syncthreads();
#pragma unroll 8
        for (int k = 0; k < 64; k++) {
            float a[4], bb[4];
#pragma unroll
            for (int i = 0; i < 4; i++) {
                a[i]  = Ps[ty * 4 + i][k];
                bb[i] = Vs[k][tx * 4 + i];
            }
#pragma unroll
            for (int i = 0; i < 4; i++)
#pragma unroll
                for (int j = 0; j < 4; j++) c[i][j] += a[i] * bb[j];
        }
        __syncthreads();
    }
    float* O = g_ao + ((size_t)b * T_ + i0) * D_ + h * DH_;
#pragma unroll
    for (int i = 0; i < 4; i++)
#pragma unroll
        for (int j = 0; j < 4; j++)
            O[(size_t)(ty * 4 + i) * D_ + tx * 4 + j] = c[i][j];
}

// ---------------- new_mem copy (== x exactly) ------------------------------
__global__ void copy_kernel(const float* __restrict__ src, float* __restrict__ dst) {
    size_t i = (size_t)blockIdx.x * 256 + threadIdx.x;
    dst[i] = src[i];
}

// ---------------- launch ---------------------------------------------------
extern "C" void kernel_launch(void* const* d_in, const int* in_sizes, int n_in,
                              void* d_out, int out_size) {
    const float* x    = (const float*)d_in[0];
    const float* mem  = (const float*)d_in[1];
    const float* Wq   = (const float*)d_in[2];
    const float* Wk   = (const float*)d_in[3];
    const float* Wv   = (const float*)d_in[4];
    const float* Wr   = (const float*)d_in[5];
    const float* Wo   = (const float*)d_in[6];
    const float* bu   = (const float*)d_in[7];
    const float* bv   = (const float*)d_in[8];
    const float* ln1g = (const float*)d_in[9];
    const float* ln1b = (const float*)d_in[10];
    const float* ln2g = (const float*)d_in[11];
    const float* ln2b = (const float*)d_in[12];
    const float* W1   = (const float*)d_in[13];
    const float* b1   = (const float*)d_in[14];
    const float* W2   = (const float*)d_in[15];
    const float* b2   = (const float*)d_in[16];
    float* out = (float*)d_out;

    float *xn, *cat, *q, *k, *v, *pe, *r, *sc, *rel, *ao, *x2, *xf, *ffh;
    cudaGetSymbolAddress((void**)&xn,  g_xn);
    cudaGetSymbolAddress((void**)&cat, g_cat);
    cudaGetSymbolAddress((void**)&q,   g_q);
    cudaGetSymbolAddress((void**)&k,   g_k);
    cudaGetSymbolAddress((void**)&v,   g_v);
    cudaGetSymbolAddress((void**)&pe,  g_pe);
    cudaGetSymbolAddress((void**)&r,   g_r);
    cudaGetSymbolAddress((void**)&sc,  g_sc);
    cudaGetSymbolAddress((void**)&rel, g_rel);
    cudaGetSymbolAddress((void**)&ao,  g_ao);
    cudaGetSymbolAddress((void**)&x2,  g_x2);
    cudaGetSymbolAddress((void**)&xf,  g_xf);
    cudaGetSymbolAddress((void**)&ffh, g_ffh);

    // positional embedding + LN1 + concat
    posemb_kernel<<<(L_ * D_ + 255) / 256, 256>>>();
    ln_kernel<<<B_ * T_, 256>>>(x, xn, ln1g, ln1b);
    concat_kernel<<<(B_ * L_ * D_) / 256, 256>>>(mem);

    // projections
    gemm_kernel<0><<<dim3(D_ / 128, (B_ * L_) / 128), 256>>>(cat, Wk, k, B_ * L_, D_, D_, nullptr, nullptr);
    gemm_kernel<0><<<dim3(D_ / 128, (B_ * L_) / 128), 256>>>(cat, Wv, v, B_ * L_, D_, D_, nullptr, nullptr);
    gemm_kernel<0><<<dim3(D_ / 128, (B_ * T_) / 128), 256>>>(xn, Wq, q, B_ * T_, D_, D_, nullptr, nullptr);
    gemm_kernel<0><<<dim3(D_ / 128, L_ / 128), 256>>>(pe, Wr, r, L_, D_, D_, nullptr, nullptr);

    // scores
    score_kernel<<<dim3(T_ / 64, L_ / 64, B_ * H_), 256>>>(q, bu, k, (size_t)L_ * D_, sc);
    score_kernel<<<dim3(T_ / 64, L_ / 64, B_ * H_), 256>>>(q, bv, r, (size_t)0, rel);

    // fused shift + softmax (in place on g_sc)
    softmax_kernel<<<B_ * H_ * T_, 256>>>();

    // attn @ V
    pv_kernel<<<dim3(T_ / 64, B_ * H_), 256>>>();

    // output projection + residual
    gemm_kernel<3><<<dim3(D_ / 128, (B_ * T_) / 128), 256>>>(ao, Wo, x2, B_ * T_, D_, D_, nullptr, x);

    // LN2 + FFN
    ln_kernel<<<B_ * T_, 256>>>(x2, xf, ln2g, ln2b);
    gemm_kernel<2><<<dim3(DFF_ / 128, (B_ * T_) / 128), 256>>>(xf, W1, ffh, B_ * T_, DFF_, D_, b1, nullptr);
    gemm_kernel<4><<<dim3(D_ / 128, (B_ * T_) / 128), 256>>>(ffh, W2, out, B_ * T_, D_, DFF_, b2, x2);

    // new_mem == x (concat([mem, x])[:, -1024:])
    if (out_size >= 2 * B_ * T_ * D_)
        copy_kernel<<<(B_ * T_ * D_) / 256, 256>>>(x, out + (size_t)B_ * T_ * D_);
}

// round 5
// speedup vs baseline: 1.2298x; 1.2298x over previous
#include <cuda_runtime.h>
#include <math.h>
#include <stdint.h>

// Problem dims (fixed by the reference)
#define B_   4
#define T_   1024
#define MM_  1024
#define D_   1024
#define H_   16
#define DH_  64
#define L_   2048
#define DFF_ 4096

// ---------------- scratch ---------------------------------------------------
__device__ float g_xn [B_*T_*D_];
__device__ float g_cat[B_*L_*D_];
__device__ float g_q  [B_*T_*D_];
__device__ float g_k  [B_*L_*D_];
__device__ float g_v  [B_*L_*D_];
__device__ float g_pe [L_*D_];
__device__ float g_r  [L_*D_];
__device__ float g_sc [B_*H_*T_*L_];
__device__ float g_rel[B_*H_*T_*L_];
__device__ float g_ao [B_*T_*D_];
__device__ float g_x2 [B_*T_*D_];
__device__ float g_xf [B_*T_*D_];
__device__ float g_ffh[B_*T_*DFF_];

// ---------------- tf32 helpers ---------------------------------------------
__device__ __forceinline__ uint32_t f2tf32(float x) {
    uint32_t r; asm("cvt.rna.tf32.f32 %0, %1;" : "=r"(r) : "f"(x)); return r;
}
__device__ __forceinline__ void split3(float x, uint32_t& hi, uint32_t& lo) {
    hi = f2tf32(x);
    lo = f2tf32(x - __uint_as_float(hi));
}
__device__ __forceinline__ void mma8(float* c, const uint32_t* a, const uint32_t* b) {
    asm volatile("mma.sync.aligned.m16n8k8.row.col.f32.tf32.tf32.f32 "
        "{%0,%1,%2,%3},{%4,%5,%6,%7},{%8,%9},{%0,%1,%2,%3};"
        : "+f"(c[0]), "+f"(c[1]), "+f"(c[2]), "+f"(c[3])
        : "r"(a[0]), "r"(a[1]), "r"(a[2]), "r"(a[3]), "r"(b[0]), "r"(b[1]));
}

// ---------------- positional embedding --------------------------------------
__global__ void posemb_kernel() {
    int idx = blockIdx.x * 256 + threadIdx.x;
    if (idx >= L_ * D_) return;
    int l = idx / D_, d = idx % D_;
    int i = (d < D_ / 2) ? d : d - D_ / 2;
    float inv = (float)(1.0 / pow(10000.0, (2.0 * i) / (double)D_));
    float pos = (float)(L_ - 1 - l);
    float arg = pos * inv;
    double s = (d < D_ / 2) ? sin((double)arg) : cos((double)arg);
    g_pe[idx] = (float)s;
}

// ---------------- layer norm -------------------------------------------------
__global__ void ln_kernel(const float* __restrict__ in, float* __restrict__ out,
                          const float* __restrict__ g, const float* __restrict__ b) {
    __shared__ float red[256];
    int row = blockIdx.x, tid = threadIdx.x;
    const float* p = in + (size_t)row * D_;
    float v[4];
    float s = 0.f;
#pragma unroll
    for (int j = 0; j < 4; j++) { v[j] = p[tid + j * 256]; s += v[j]; }
    red[tid] = s; __syncthreads();
    for (int o = 128; o > 0; o >>= 1) { if (tid < o) red[tid] += red[tid + o]; __syncthreads(); }
    float mu = red[0] * (1.0f / D_);
    __syncthreads();
    float vs = 0.f;
#pragma unroll
    for (int j = 0; j < 4; j++) { float dd = v[j] - mu; vs += dd * dd; }
    red[tid] = vs; __syncthreads();
    for (int o = 128; o > 0; o >>= 1) { if (tid < o) red[tid] += red[tid + o]; __syncthreads(); }
    float inv = rsqrtf(red[0] * (1.0f / D_) + 1e-5f);
    float* q = out + (size_t)row * D_;
#pragma unroll
    for (int j = 0; j < 4; j++) {
        int c = tid + j * 256;
        q[c] = (v[j] - mu) * inv * g[c] + b[c];
    }
}

// ---------------- concat -----------------------------------------------------
__global__ void concat_kernel(const float* __restrict__ mem) {
    size_t idx = (size_t)blockIdx.x * 256 + threadIdx.x;
    int b = (int)(idx / ((size_t)L_ * D_));
    int rem = (int)(idx % ((size_t)L_ * D_));
    int l = rem / D_, d = rem % D_;
    g_cat[idx] = (l < MM_) ? mem[((size_t)b * MM_ + l) * D_ + d]
                           : g_xn[((size_t)b * T_ + (l - MM_)) * D_ + d];
}

// ---------------- dense tf32 mma GEMM (128x128 block, 256 thr) ---------------
// epi (runtime): 0 none, 1 +bias, 2 gelu(.+bias), 3 +res, 4 +bias+res
__device__ __forceinline__ float gelu_exact(float x) {
    return 0.5f * x * (1.0f + erff(x * 0.70710678118654752f));
}

__global__ __launch_bounds__(256)
void mma_gemm(const float* __restrict__ A, const float* __restrict__ Bp,
              float* __restrict__ C, int M, int N, int K, int epi,
              const float* __restrict__ bias, const float* __restrict__ res) {
    __shared__ float As[128][36];
    __shared__ float Bs[32][136];
    int tid = threadIdx.x;
    int lane = tid & 31, wid = tid >> 5;
    int g = lane >> 2, t4 = lane & 3;
    int wm = (wid >> 2) * 64;
    int wn = (wid & 3) * 32;
    int bm = blockIdx.y * 128, bn = blockIdx.x * 128;
    float acc[4][4][4] = {};
    for (int k0 = 0; k0 < K; k0 += 32) {
#pragma unroll
        for (int i = 0; i < 4; i++) {
            int id = tid + 256 * i;
            int row = id >> 3, c4 = (id & 7) << 2;
            float4 va = *(const float4*)&A[(size_t)(bm + row) * K + k0 + c4];
            *(float4*)&As[row][c4] = va;
            int brow = id >> 5, bc4 = (id & 31) << 2;
            float4 vb = *(const float4*)&Bp[(size_t)(k0 + brow) * N + bn + bc4];
            *(float4*)&Bs[brow][bc4] = vb;
        }
        __syncthreads();
#pragma unroll
        for (int kk = 0; kk < 32; kk += 8) {
            uint32_t aH[4][4], aL[4][4], bH[4][2], bL[4][2];
#pragma unroll
            for (int mt = 0; mt < 4; mt++) {
                int r0 = wm + mt * 16 + g;
                split3(As[r0][kk + t4],         aH[mt][0], aL[mt][0]);
                split3(As[r0 + 8][kk + t4],     aH[mt][1], aL[mt][1]);
                split3(As[r0][kk + t4 + 4],     aH[mt][2], aL[mt][2]);
                split3(As[r0 + 8][kk + t4 + 4], aH[mt][3], aL[mt][3]);
            }
#pragma unroll
            for (int nt = 0; nt < 4; nt++) {
                int c0 = wn + nt * 8 + g;
                split3(Bs[kk + t4][c0],     bH[nt][0], bL[nt][0]);
                split3(Bs[kk + t4 + 4][c0], bH[nt][1], bL[nt][1]);
            }
#pragma unroll
            for (int mt = 0; mt < 4; mt++)
#pragma unroll
                for (int nt = 0; nt < 4; nt++) {
                    mma8(acc[mt][nt], aH[mt], bH[nt]);
                    mma8(acc[mt][nt], aH[mt], bL[nt]);
                    mma8(acc[mt][nt], aL[mt], bH[nt]);
                }
        }
        __syncthreads();
    }
#pragma unroll
    for (int mt = 0; mt < 4; mt++)
#pragma unroll
        for (int nt = 0; nt < 4; nt++)
#pragma unroll
            for (int e = 0; e < 4; e++) {
                int row = bm + wm + mt * 16 + g + ((e >= 2) ? 8 : 0);
                int col = bn + wn + nt * 8 + t4 * 2 + (e & 1);
                float v = acc[mt][nt][e];
                if (epi == 1) v += bias[col];
                else if (epi == 2) v = gelu_exact(v + bias[col]);
                else if (epi == 3) v += res[(size_t)row * N + col];
                else if (epi == 4) v += bias[col] + res[(size_t)row * N + col];
                C[(size_t)row * N + col] = v;
            }
}

// ---------------- batched score GEMM: C[bh,T,L] = (q+bias) @ km^T ------------
// km row-major [j, h*64+d] (row stride D_), per-batch stride bstride (0 for r)
__global__ __launch_bounds__(256)
void mma_score(const float* __restrict__ Q, const float* __restrict__ bias,
               const float* __restrict__ Bm, size_t bstride,
               float* __restrict__ C) {
    __shared__ float As[128][36];
    __shared__ float Bs[32][136];
    int bh = blockIdx.z, b = bh >> 4, h = bh & 15;
    int i0 = blockIdx.y * 128, j0 = blockIdx.x * 128;
    const float* qp = Q + (size_t)b * T_ * D_ + h * DH_;
    const float* bp = Bm + (size_t)b * bstride + h * DH_;
    const float* up = bias + h * DH_;
    int tid = threadIdx.x;
    int lane = tid & 31, wid = tid >> 5;
    int g = lane >> 2, t4 = lane & 3;
    int wm = (wid >> 2) * 64;
    int wn = (wid & 3) * 32;
    float acc[4][4][4] = {};
    for (int k0 = 0; k0 < DH_; k0 += 32) {
#pragma unroll
        for (int i = 0; i < 4; i++) {
            int id = tid + 256 * i;
            int row = id >> 3, c4 = (id & 7) << 2;
            float4 va = *(const float4*)&qp[(size_t)(i0 + row) * D_ + k0 + c4];
            float4 vu = *(const float4*)&up[k0 + c4];
            va.x += vu.x; va.y += vu.y; va.z += vu.z; va.w += vu.w;
            *(float4*)&As[row][c4] = va;
            // B transposed: Bs[k][n] = km[j0+n][k0+k]
            float4 vb = *(const float4*)&bp[(size_t)(j0 + row) * D_ + k0 + c4];
            Bs[c4 + 0][row] = vb.x;
            Bs[c4 + 1][row] = vb.y;
            Bs[c4 + 2][row] = vb.z;
            Bs[c4 + 3][row] = vb.w;
        }
        __syncthreads();
#pragma unroll
        for (int kk = 0; kk < 32; kk += 8) {
            uint32_t aH[4][4], aL[4][4], bH[4][2], bL[4][2];
#pragma unroll
            for (int mt = 0; mt < 4; mt++) {
                int r0 = wm + mt * 16 + g;
                split3(As[r0][kk + t4],         aH[mt][0], aL[mt][0]);
                split3(As[r0 + 8][kk + t4],     aH[mt][1], aL[mt][1]);
                split3(As[r0][kk + t4 + 4],     aH[mt][2], aL[mt][2]);
                split3(As[r0 + 8][kk + t4 + 4], aH[mt][3], aL[mt][3]);
            }
#pragma unroll
            for (int nt = 0; nt < 4; nt++) {
                int c0 = wn + nt * 8 + g;
                split3(Bs[kk + t4][c0],     bH[nt][0], bL[nt][0]);
                split3(Bs[kk + t4 + 4][c0], bH[nt][1], bL[nt][1]);
            }
#pragma unroll
            for (int mt = 0; mt < 4; mt++)
#pragma unroll
                for (int nt = 0; nt < 4; nt++) {
                    mma8(acc[mt][nt], aH[mt], bH[nt]);
                    mma8(acc[mt][nt], aH[mt], bL[nt]);
                    mma8(acc[mt][nt], aL[mt], bH[nt]);
                }
        }
        __syncthreads();
    }
    float* cb = C + (size_t)bh * T_ * L_;
#pragma unroll
    for (int mt = 0; mt < 4; mt++)
#pragma unroll
        for (int nt = 0; nt < 4; nt++)
#pragma unroll
            for (int e = 0; e < 4; e++) {
                int row = i0 + wm + mt * 16 + g + ((e >= 2) ? 8 : 0);
                int col = j0 + wn + nt * 8 + t4 * 2 + (e & 1);
                cb[(size_t)row * L_ + col] = acc[mt][nt][e];
            }
}

// ---------------- fused rel-shift + add + scale + softmax --------------------
__global__ __launch_bounds__(256)
void softmax_kernel() {
    int row = blockIdx.x;
    int bh = row >> 10;
    int i  = row & 1023;
    size_t base = (size_t)bh * T_ * L_;
    float* P = g_sc + base + (size_t)i * L_;
    const float* R = g_rel + base;
    __shared__ float red[8];
    int tid = threadIdx.x;
    int lane = tid & 31, wid = tid >> 5;
    float v[8];
    float mx = -1e30f;
#pragma unroll
    for (int jj = 0; jj < 8; jj++) {
        int j = tid + (jj << 8);
        int f = i * L_ + j + T_;
        int i2 = f / (L_ + 1);
        int l = f - i2 * (L_ + 1);
        float rv = (l > 0) ? R[(size_t)i2 * L_ + (l - 1)] : 0.0f;
        float s = (P[j] + rv) * 0.125f;
        v[jj] = s;
        mx = fmaxf(mx, s);
    }
#pragma unroll
    for (int o = 16; o > 0; o >>= 1) mx = fmaxf(mx, __shfl_xor_sync(0xffffffffu, mx, o));
    if (lane == 0) red[wid] = mx;
    __syncthreads();
    mx = red[0];
#pragma unroll
    for (int w = 1; w < 8; w++) mx = fmaxf(mx, red[w]);
    float sum = 0.f;
#pragma unroll
    for (int jj = 0; jj < 8; jj++) { v[jj] = expf(v[jj] - mx); sum += v[jj]; }
#pragma unroll
    for (int o = 16; o > 0; o >>= 1) sum += __shfl_xor_sync(0xffffffffu, sum, o);
    __syncthreads();
    if (lane == 0) red[wid] = sum;
    __syncthreads();
    sum = 0.f;
#pragma unroll
    for (int w = 0; w < 8; w++) sum += red[w];
    float inv = 1.0f / sum;
#pragma unroll
    for (int jj = 0; jj < 8; jj++) P[tid + (jj << 8)] = v[jj] * inv;
}

// ---------------- probs @ V (batched, 64x64 block, 128 thr) ------------------
__global__ __launch_bounds__(128)
void mma_pv() {
    __shared__ float As[64][36];
    __shared__ float Bs[32][72];
    int bh = blockIdx.y, b = bh >> 4, h = bh & 15;
    int i0 = blockIdx.x * 64;
    const float* P = g_sc + (size_t)bh * T_ * L_;
    const float* V = g_v + (size_t)b * L_ * D_ + h * DH_;
    int tid = threadIdx.x;
    int lane = tid & 31, wid = tid >> 5;
    int g = lane >> 2, t4 = lane & 3;
    int wm = (wid >> 1) * 32;
    int wn = (wid & 1) * 32;
    float acc[2][4][4] = {};
    for (int k0 = 0; k0 < L_; k0 += 32) {
#pragma unroll
        for (int i = 0; i < 4; i++) {
            int id = tid + 128 * i;
            int row = id >> 3, c4 = (id & 7) << 2;
            float4 va = *(const float4*)&P[(size_t)(i0 + row) * L_ + k0 + c4];
            *(float4*)&As[row][c4] = va;
            int brow = id >> 4, bc4 = (id & 15) << 2;
            float4 vb = *(const float4*)&V[(size_t)(k0 + brow) * D_ + bc4];
            *(float4*)&Bs[brow][bc4] = vb;
        }
        __syncthreads();
#pragma unroll
        for (int kk = 0; kk < 32; kk += 8) {
            uint32_t aH[2][4], aL[2][4], bH[4][2], bL[4][2];
#pragma unroll
            for (int mt = 0; mt < 2; mt++) {
                int r0 = wm + mt * 16 + g;
                split3(As[r0][kk + t4],         aH[mt][0], aL[mt][0]);
                split3(As[r0 + 8][kk + t4],     aH[mt][1], aL[mt][1]);
                split3(As[r0][kk + t4 + 4],     aH[mt][2], aL[mt][2]);
                split3(As[r0 + 8][kk + t4 + 4], aH[mt][3], aL[mt][3]);
            }
#pragma unroll
            for (int nt = 0; nt < 4; nt++) {
                int c0 = wn + nt * 8 + g;
                split3(Bs[kk + t4][c0],     bH[nt][0], bL[nt][0]);
                split3(Bs[kk + t4 + 4][c0], bH[nt][1], bL[nt][1]);
            }
#pragma unroll
            for (int mt = 0; mt < 2; mt++)
#pragma unroll
                for (int nt = 0; nt < 4; nt++) {
                    mma8(acc[mt][nt], aH[mt], bH[nt]);
                    mma8(acc[mt][nt], aH[mt], bL[nt]);
                    mma8(acc[mt][nt], aL[mt], bH[nt]);
                }
        }
        __syncthreads();
    }
#pragma unroll
    for (int mt = 0; mt < 2; mt++)
#pragma unroll
        for (int nt = 0; nt < 4; nt++)
#pragma unroll
            for (int e = 0; e < 4; e++) {
                int row = i0 + wm + mt * 16 + g + ((e >= 2) ? 8 : 0);
                int col = wn + nt * 8 + t4 * 2 + (e & 1);
                g_ao[((size_t)b * T_ + row) * D_ + h * DH_ + col] = acc[mt][nt][e];
            }
}

// ---------------- new_mem copy ----------------------------------------------
__global__ void copy_kernel(const float* __restrict__ src, float* __restrict__ dst) {
    size_t i = (size_t)blockIdx.x * 256 + threadIdx.x;
    dst[i] = src[i];
}

// ---------------- launch -----------------------------------------------------
extern "C" void kernel_launch(void* const* d_in, const int* in_sizes, int n_in,
                              void* d_out, int out_size) {
    const float* x    = (const float*)d_in[0];
    const float* mem  = (const float*)d_in[1];
    const float* Wq   = (const float*)d_in[2];
    const float* Wk   = (const float*)d_in[3];
    const float* Wv   = (const float*)d_in[4];
    const float* Wr   = (const float*)d_in[5];
    const float* Wo   = (const float*)d_in[6];
    const float* bu   = (const float*)d_in[7];
    const float* bv   = (const float*)d_in[8];
    const float* ln1g = (const float*)d_in[9];
    const float* ln1b = (const float*)d_in[10];
    const float* ln2g = (const float*)d_in[11];
    const float* ln2b = (const float*)d_in[12];
    const float* W1   = (const float*)d_in[13];
    const float* b1   = (const float*)d_in[14];
    const float* W2   = (const float*)d_in[15];
    const float* b2   = (const float*)d_in[16];
    float* out = (float*)d_out;

    float *xn, *cat, *q, *k, *v, *pe, *r, *sc, *rel, *x2, *xf, *ffh, *ao;
    cudaGetSymbolAddress((void**)&xn,  g_xn);
    cudaGetSymbolAddress((void**)&cat, g_cat);
    cudaGetSymbolAddress((void**)&q,   g_q);
    cudaGetSymbolAddress((void**)&k,   g_k);
    cudaGetSymbolAddress((void**)&v,   g_v);
    cudaGetSymbolAddress((void**)&pe,  g_pe);
    cudaGetSymbolAddress((void**)&r,   g_r);
    cudaGetSymbolAddress((void**)&sc,  g_sc);
    cudaGetSymbolAddress((void**)&rel, g_rel);
    cudaGetSymbolAddress((void**)&ao,  g_ao);
    cudaGetSymbolAddress((void**)&x2,  g_x2);
    cudaGetSymbolAddress((void**)&xf,  g_xf);
    cudaGetSymbolAddress((void**)&ffh, g_ffh);

    posemb_kernel<<<(L_ * D_ + 255) / 256, 256>>>();
    ln_kernel<<<B_ * T_, 256>>>(x, xn, ln1g, ln1b);
    concat_kernel<<<(B_ * L_ * D_) / 256, 256>>>(mem);

    // projections (tf32 3x mma)
    mma_gemm<<<dim3(D_ / 128, (B_ * L_) / 128), 256>>>(cat, Wk, k, B_ * L_, D_, D_, 0, nullptr, nullptr);
    mma_gemm<<<dim3(D_ / 128, (B_ * L_) / 128), 256>>>(cat, Wv, v, B_ * L_, D_, D_, 0, nullptr, nullptr);
    mma_gemm<<<dim3(D_ / 128, (B_ * T_) / 128), 256>>>(xn, Wq, q, B_ * T_, D_, D_, 0, nullptr, nullptr);
    mma_gemm<<<dim3(D_ / 128, L_ / 128), 256>>>(pe, Wr, r, L_, D_, D_, 0, nullptr, nullptr);

    // scores
    mma_score<<<dim3(L_ / 128, T_ / 128, B_ * H_), 256>>>(q, bu, k, (size_t)L_ * D_, sc);
    mma_score<<<dim3(L_ / 128, T_ / 128, B_ * H_), 256>>>(q, bv, r, (size_t)0, rel);

    softmax_kernel<<<B_ * H_ * T_, 256>>>();

    mma_pv<<<dim3(T_ / 64, B_ * H_), 128>>>();

    // output projection + residual
    mma_gemm<<<dim3(D_ / 128, (B_ * T_) / 128), 256>>>(ao, Wo, x2, B_ * T_, D_, D_, 3, nullptr, x);

    // LN2 + FFN
    ln_kernel<<<B_ * T_, 256>>>(x2, xf, ln2g, ln2b);
    mma_gemm<<<dim3(DFF_ / 128, (B_ * T_) / 128), 256>>>(xf, W1, ffh, B_ * T_, DFF_, D_, 2, b1, nullptr);
    mma_gemm<<<dim3(D_ / 128, (B_ * T_) / 128), 256>>>(ffh, W2, out, B_ * T_, D_, DFF_, 4, b2, x2);

    // new_mem == x
    if (out_size >= 2 * B_ * T_ * D_)
        copy_kernel<<<(B_ * T_ * D_) / 256, 256>>>(x, out + (size_t)B_ * T_ * D_);
}